// round 4
// baseline (speedup 1.0000x reference)
#include <cuda_runtime.h>

// Soft-DTW, gamma = 0.01, p = 2, B = 64, M = N = 512.
// One CTA per batch; thread j owns column j; anti-diagonal wavefront with a
// ping-pong shared row and one __syncthreads per diagonal step.
//
// softmin3(a,b,c) = m - gamma * ln(1 + exp(-(v1-m)/g) + exp(-(v2-m)/g)),
// m = min, {v1,v2} the other two. Computed via MUFU ex2/lg2:
//   arg = (m - v) * 100 * log2(e);  softmin = m - (0.01*ln2) * log2(1+e1+e2)

#define BIG   1e30f
#define KEXP  144.26950408889634f    // 100 * log2(e)
#define GLN2  0.006931471805599453f  // 0.01 * ln(2)

__device__ __forceinline__ float ex2f_(float v) {
    float r; asm("ex2.approx.ftz.f32 %0, %1;" : "=f"(r) : "f"(v)); return r;
}
__device__ __forceinline__ float lg2f_(float v) {
    float r; asm("lg2.approx.ftz.f32 %0, %1;" : "=f"(r) : "f"(v)); return r;
}

__global__ __launch_bounds__(512, 1)
void softdtw_kernel(const float* __restrict__ x,
                    const float* __restrict__ y,
                    float* __restrict__ out)
{
    __shared__ float ysh[512];
    __shared__ float buf0[513];   // [0] = left border (BIG), [1+j] = thread j's R
    __shared__ float buf1[513];

    const int b = blockIdx.x;
    const int j = threadIdx.x;

    ysh[j] = y[b * 512 + j];
    const float xj = x[b * 512 + j];
    if (j == 0) { buf0[0] = BIG; buf1[0] = BIG; }

    // diag = R[i-1, j-1] carried from the previous step's left-read.
    // r_up = R[i-1, j] (this thread's previous result).
    float diag = (j == 0) ? 0.0f : BIG;   // R[-1,-1] = 0, else R[-1,j-1] = +inf
    float r_up = BIG;                     // R[-1, j]  = +inf

    __syncthreads();

    // At step s, thread j computes cell (i = s - j, j), reading the left
    // neighbor's step-(s-1) value from PRV and writing its own into CUR.
#define STEP(S, PRV, CUR) do {                                          \
        unsigned ii = (unsigned)((S) - j);                              \
        if (ii < 512u) {                                                \
            float left = PRV[j];            /* R[i, j-1]   */           \
            float yv   = ysh[ii];                                       \
            float t    = xj - yv;                                       \
            float dd   = t * t;             /* cost d[i,j] */           \
            float t1 = fminf(diag, r_up);                               \
            float t2 = fmaxf(diag, r_up);                               \
            float m  = fminf(t1, left);     /* min of 3     */          \
            float u  = fmaxf(t1, left);     /* 2nd smallest */          \
            float mk = m * KEXP;                                        \
            float a1 = fmaf(-KEXP, t2, mk); /* (m-t2)*K <= 0 */         \
            float a2 = fmaf(-KEXP, u,  mk); /* (m-u)*K  <= 0 */         \
            float ss = 1.0f + ex2f_(a1) + ex2f_(a2);                    \
            float r  = dd + fmaf(-GLN2, lg2f_(ss), m);                  \
            CUR[j + 1] = r;                                             \
            diag = left;                                                \
            r_up = r;                                                   \
        }                                                               \
        __syncthreads();                                                \
    } while (0)

    // 1023 real diagonal steps; step 1023 is a no-op for every thread
    // (keeps the unroll-by-2 ping-pong clean).
    for (int s = 0; s < 1024; s += 2) {
        STEP(s,     buf0, buf1);
        STEP(s + 1, buf1, buf0);
    }
#undef STEP

    if (j == 511) out[b] = r_up;   // R[511, 511]
}

extern "C" void kernel_launch(void* const* d_in, const int* in_sizes, int n_in,
                              void* d_out, int out_size)
{
    const float* x = (const float*)d_in[0];
    const float* y = (const float*)d_in[1];
    float* out = (float*)d_out;
    softdtw_kernel<<<64, 512>>>(x, y, out);
}